// round 4
// baseline (speedup 1.0000x reference)
#include <cuda_runtime.h>
#include <cuda_bf16.h>

#define NN 16384
#define VV 16384
#define EE 524288
#define HH 8
#define DD 64
#define HD 512
#define EMBD 16
#define NC 40

// ---- scratch (device globals; allocation is forbidden) ----
__device__ __align__(128) float g_xemb[NN * EMBD];
__device__ __align__(128) float g_h[NN * HD];     // transformed features (x @ W)
__device__ __align__(128) float g_x[NN * HD];     // layer output (post edge-agg + LN)
__device__ __align__(128) float g_s1[NN * HH];
__device__ __align__(128) float g_s2[NN * HH];
__device__ __align__(128) float g_Wp[HD * HD];    // packed W: [k][h*64+d]
__device__ int g_rowptr[NN + 1];

// ---- row_ptr from sorted edge_row via binary search ----
__global__ void k_rowptr(const int* __restrict__ er) {
    int r = blockIdx.x * blockDim.x + threadIdx.x;
    if (r > NN) return;
    int lo = 0, hi = EE;
    while (lo < hi) { int mid = (lo + hi) >> 1; if (er[mid] < r) lo = mid + 1; else hi = mid; }
    g_rowptr[r] = lo;
}

// ---- x = LN(x_in @ emb): 16 rows per block, 256 thr = 4 rowgroups x 64 v-lanes ----
__global__ void k_emb(const float* __restrict__ xin, const float* __restrict__ emb) {
    const int tid = threadIdx.x;
    const int rg = tid >> 6;        // rowgroup 0..3 (4 rows each)
    const int vl = tid & 63;        // v-lane
    const int R0 = blockIdx.x << 4;

    float acc[4][16];
#pragma unroll
    for (int r = 0; r < 4; ++r)
#pragma unroll
        for (int c = 0; c < 16; ++c) acc[r][c] = 0.f;

    const size_t xbase = (size_t)(R0 + rg * 4) * VV;
    for (int it = 0; it < VV / 64; ++it) {
        const int v = vl + (it << 6);
        const float4* ep = (const float4*)(emb + (size_t)v * EMBD);
        float4 e0 = ep[0], e1 = ep[1], e2 = ep[2], e3 = ep[3];
        float ev[16] = {e0.x,e0.y,e0.z,e0.w, e1.x,e1.y,e1.z,e1.w,
                        e2.x,e2.y,e2.z,e2.w, e3.x,e3.y,e3.z,e3.w};
#pragma unroll
        for (int r = 0; r < 4; ++r) {
            float xv = xin[xbase + (size_t)r * VV + v];
#pragma unroll
            for (int c = 0; c < 16; ++c) acc[r][c] += xv * ev[c];
        }
    }
    // reduce over 64 v-lanes: warp butterfly, then 2 warp-halves via shared
    const int lane = tid & 31;
#pragma unroll
    for (int s = 16; s > 0; s >>= 1)
#pragma unroll
        for (int r = 0; r < 4; ++r)
#pragma unroll
            for (int c = 0; c < 16; ++c)
                acc[r][c] += __shfl_xor_sync(0xffffffffu, acc[r][c], s);

    __shared__ float red[4][2][64];   // [rowgroup][warp-half][r*16+c]
    __shared__ float sval[16][17];
    __shared__ float smu[16], srs[16];
    const int half = vl >> 5;
    if (lane == 0) {
#pragma unroll
        for (int r = 0; r < 4; ++r)
#pragma unroll
            for (int c = 0; c < 16; ++c) red[rg][half][r * 16 + c] = acc[r][c];
    }
    __syncthreads();
    {
        const int rl = tid >> 4, c = tid & 15;   // 16 rows x 16 cols
        sval[rl][c] = red[rl >> 2][0][(rl & 3) * 16 + c] + red[rl >> 2][1][(rl & 3) * 16 + c];
    }
    __syncthreads();
    if (tid < 16) {
        float s = 0.f;
#pragma unroll
        for (int c = 0; c < 16; ++c) s += sval[tid][c];
        float mu = s * (1.f / 16);
        float var = 0.f;
#pragma unroll
        for (int c = 0; c < 16; ++c) { float d = sval[tid][c] - mu; var += d * d; }
        smu[tid] = mu;
        srs[tid] = rsqrtf(var * (1.f / 16) + 1e-5f);
    }
    __syncthreads();
    {
        const int rl = tid >> 4, c = tid & 15;
        g_xemb[(size_t)(R0 + rl) * EMBD + c] = (sval[rl][c] - smu[rl]) * srs[rl];
    }
}

// ---- layer-1: g_h = g_xemb (N,16) @ W1, W1 (H,16,64) -> cols h*64+d ----
__global__ void k_h1(const float* __restrict__ W1) {
    __shared__ float Ws[EMBD][HD];    // [k][h*64+d]
    __shared__ float xs[16][EMBD];
    const int tid = threadIdx.x;
    for (int i = tid; i < HH * EMBD * DD; i += 256) {
        int h = i >> 10, k = (i >> 6) & 15, d = i & 63;
        Ws[k][h * DD + d] = W1[i];
    }
    const int n0 = blockIdx.x << 4;   // 16 nodes per block
    for (int i = tid; i < 16 * EMBD; i += 256)
        xs[i >> 4][i & 15] = g_xemb[(size_t)n0 * EMBD + i];
    __syncthreads();
    const int c0 = tid * 2;
    for (int nl = 0; nl < 16; ++nl) {
        float a0 = 0.f, a1 = 0.f;
#pragma unroll
        for (int k = 0; k < EMBD; ++k) {
            float xv = xs[nl][k];
            a0 += xv * Ws[k][c0];
            a1 += xv * Ws[k][c0 + 1];
        }
        float2 o = make_float2(a0, a1);
        ((float2*)g_h)[(size_t)(n0 + nl) * 256 + tid] = o;
    }
}

// ---- per-node attention scalars: s1 = h . a[:,:64], s2 = h . a[:,64:] ----
__global__ void k_s(const float* __restrict__ av) {
    const int warp = threadIdx.x >> 5, lane = threadIdx.x & 31;
    const int n = (blockIdx.x << 3) + warp;
    const int h = lane >> 2, part = lane & 3;      // 4 lanes per head, 16 elems each
    const float4* hp = (const float4*)(g_h + (size_t)n * HD + h * DD + part * 16);
    const float* a1 = av + h * 2 * DD + part * 16;
    const float* a2 = a1 + DD;
    float s1 = 0.f, s2 = 0.f;
#pragma unroll
    for (int j = 0; j < 4; ++j) {
        float4 hv = hp[j];
        s1 += hv.x * a1[4*j] + hv.y * a1[4*j+1] + hv.z * a1[4*j+2] + hv.w * a1[4*j+3];
        s2 += hv.x * a2[4*j] + hv.y * a2[4*j+1] + hv.z * a2[4*j+2] + hv.w * a2[4*j+3];
    }
    s1 += __shfl_xor_sync(0xffffffffu, s1, 1); s1 += __shfl_xor_sync(0xffffffffu, s1, 2);
    s2 += __shfl_xor_sync(0xffffffffu, s2, 1); s2 += __shfl_xor_sync(0xffffffffu, s2, 2);
    if (part == 0) { g_s1[n * HH + h] = s1; g_s2[n * HH + h] = s2; }
}

// ---- edge aggregation + normalize + (elu) + LN(512) + (elu); warp per row ----
// mode 0: elu then LN (layers 1,2).  mode 1: LN then elu (final layer).
__global__ void k_edge(const int* __restrict__ ecol, int mode) {
    const int warp = threadIdx.x >> 5, lane = threadIdx.x & 31;
    const int n = (blockIdx.x << 3) + warp;
    const int h = lane >> 2;                      // head of this lane's 16 cols
    const int start = g_rowptr[n], end = g_rowptr[n + 1];
    const float s1v = g_s1[n * HH + h];

    float acc[16];
#pragma unroll
    for (int j = 0; j < 16; ++j) acc[j] = 0.f;
    float rsum = 0.f;

    for (int e = start; e < end; ++e) {
        const int c = ecol[e];
        float t = s1v + g_s2[c * HH + h];
        float lr = t > 0.f ? t : 0.2f * t;
        float ev = __expf(-lr);
        rsum += ev;
        const float4* hp = (const float4*)(g_h + (size_t)c * HD + lane * 16);
#pragma unroll
        for (int j = 0; j < 4; ++j) {
            float4 v = hp[j];
            acc[4*j]   += ev * v.x;  acc[4*j+1] += ev * v.y;
            acc[4*j+2] += ev * v.z;  acc[4*j+3] += ev * v.w;
        }
    }
    const float inv = 1.f / rsum;
    float o[16];
#pragma unroll
    for (int j = 0; j < 16; ++j) {
        float v = acc[j] * inv;
        if (mode == 0) v = v > 0.f ? v : expm1f(v);   // elu before LN
        o[j] = v;
    }
    // LayerNorm over the full 512 (warp holds the row)
    float s = 0.f, sq = 0.f;
#pragma unroll
    for (int j = 0; j < 16; ++j) { s += o[j]; sq += o[j] * o[j]; }
#pragma unroll
    for (int d = 16; d > 0; d >>= 1) {
        s  += __shfl_xor_sync(0xffffffffu, s, d);
        sq += __shfl_xor_sync(0xffffffffu, sq, d);
    }
    float mu = s * (1.f / HD);
    float var = sq * (1.f / HD) - mu * mu;
    float rs = rsqrtf(var + 1e-5f);
    float* xo = g_x + (size_t)n * HD + lane * 16;
#pragma unroll
    for (int j = 0; j < 16; ++j) {
        float v = (o[j] - mu) * rs;
        if (mode == 1) v = v > 0.f ? v : expm1f(v);   // elu after LN (final)
        xo[j] = v;
    }
}

// ---- pack W (H,512,64) -> Wp[k][h*64+d] ----
__global__ void k_pack(const float* __restrict__ W) {
    int i = blockIdx.x * 256 + threadIdx.x;
    int h = i >> 15, k = (i >> 6) & 511, d = i & 63;
    g_Wp[k * HD + (h << 6) + d] = W[i];
}

// ---- g_h = g_x (N,512) @ g_Wp (512,512); 128x128x8 tiles, 8x8 per thread ----
__global__ void k_gemm() {
    __shared__ float As[8][128];
    __shared__ float Bs[8][128];
    const int tid = threadIdx.x;
    const int tx = tid & 15, ty = tid >> 4;
    const int m0 = blockIdx.y * 128, n0 = blockIdx.x * 128;
    float acc[8][8];
#pragma unroll
    for (int i = 0; i < 8; ++i)
#pragma unroll
        for (int j = 0; j < 8; ++j) acc[i][j] = 0.f;

    const int arow = tid >> 1, acol = (tid & 1) * 4;
    const int brow = tid >> 5, bcol = (tid & 31) * 4;

    for (int k0 = 0; k0 < HD; k0 += 8) {
        float4 a = *(const float4*)(g_x + (size_t)(m0 + arow) * HD + k0 + acol);
        As[acol + 0][arow] = a.x; As[acol + 1][arow] = a.y;
        As[acol + 2][arow] = a.z; As[acol + 3][arow] = a.w;
        *(float4*)&Bs[brow][bcol] = *(const float4*)(g_Wp + (size_t)(k0 + brow) * HD + n0 + bcol);
        __syncthreads();
#pragma unroll
        for (int k = 0; k < 8; ++k) {
            float ra[8], rb[8];
#pragma unroll
            for (int i = 0; i < 8; ++i) ra[i] = As[k][ty * 8 + i];
#pragma unroll
            for (int j = 0; j < 8; ++j) rb[j] = Bs[k][tx * 8 + j];
#pragma unroll
            for (int i = 0; i < 8; ++i)
#pragma unroll
                for (int j = 0; j < 8; ++j) acc[i][j] += ra[i] * rb[j];
        }
        __syncthreads();
    }
#pragma unroll
    for (int i = 0; i < 8; ++i)
#pragma unroll
        for (int j = 0; j < 8; ++j)
            g_h[(size_t)(m0 + ty * 8 + i) * HD + n0 + tx * 8 + j] = acc[i][j];
}

// ---- classifier + log_softmax; warp per row ----
__global__ void k_out(const float* __restrict__ Wo, const float* __restrict__ bo,
                      float* __restrict__ out) {
    const int warp = threadIdx.x >> 5, lane = threadIdx.x & 31;
    const int n = (blockIdx.x << 3) + warp;
    const int c1 = 32 + (lane & 7);           // always in-bounds
    const float* xr = g_x + (size_t)n * HD;
    float a0 = 0.f, a1 = 0.f;
    for (int k = 0; k < HD; ++k) {
        float xv = xr[k];
        a0 += xv * Wo[k * NC + lane];
        a1 += xv * Wo[k * NC + c1];
    }
    float v0 = a0 + bo[lane];
    float v1 = a1 + bo[c1];
    bool use1 = lane < 8;
    // max over 40
    float m = fmaxf(v0, use1 ? v1 : -3.4e38f);
#pragma unroll
    for (int d = 16; d > 0; d >>= 1) m = fmaxf(m, __shfl_xor_sync(0xffffffffu, m, d));
    float se = expf(v0 - m) + (use1 ? expf(v1 - m) : 0.f);
#pragma unroll
    for (int d = 16; d > 0; d >>= 1) se += __shfl_xor_sync(0xffffffffu, se, d);
    float lse = m + logf(se);
    out[(size_t)n * NC + lane] = v0 - lse;
    if (use1) out[(size_t)n * NC + c1] = v1 - lse;
}

extern "C" void kernel_launch(void* const* d_in, const int* in_sizes, int n_in,
                              void* d_out, int out_size) {
    const float* x_in = (const float*)d_in[0];
    const float* emb  = (const float*)d_in[1];
    const float* W1   = (const float*)d_in[2];
    const float* a1   = (const float*)d_in[3];
    const float* W2   = (const float*)d_in[4];
    const float* a2   = (const float*)d_in[5];
    const float* Wf   = (const float*)d_in[6];
    const float* af   = (const float*)d_in[7];
    const float* Wo   = (const float*)d_in[8];
    const float* bo   = (const float*)d_in[9];
    const int* erow   = (const int*)d_in[10];
    const int* ecol   = (const int*)d_in[11];
    float* out = (float*)d_out;

    k_rowptr<<<65, 256>>>(erow);
    k_emb<<<NN / 16, 256>>>(x_in, emb);

    // layer 1
    k_h1<<<NN / 16, 256>>>(W1);
    k_s<<<NN / 8, 256>>>(a1);
    k_edge<<<NN / 8, 256>>>(ecol, 0);
    // layer 2
    k_pack<<<HD * HD / 256, 256>>>(W2);
    k_gemm<<<dim3(4, 128), 256>>>();
    k_s<<<NN / 8, 256>>>(a2);
    k_edge<<<NN / 8, 256>>>(ecol, 0);
    // final GAT layer
    k_pack<<<HD * HD / 256, 256>>>(Wf);
    k_gemm<<<dim3(4, 128), 256>>>();
    k_s<<<NN / 8, 256>>>(af);
    k_edge<<<NN / 8, 256>>>(ecol, 1);
    // classifier
    k_out<<<NN / 8, 256>>>(Wo, bo, out);
}

// round 5
// speedup vs baseline: 1.0350x; 1.0350x over previous
#include <cuda_runtime.h>
#include <cuda_bf16.h>

#define NN 16384
#define VV 16384
#define EE 524288
#define HH 8
#define DD 64
#define HD 512
#define EMBD 16
#define NC 40

typedef unsigned long long ull;

// ---- scratch (device globals; allocation is forbidden) ----
__device__ __align__(128) float g_xemb[NN * EMBD];
__device__ __align__(128) float g_h[NN * HD];     // transformed features (x @ W)
__device__ __align__(128) float g_x[NN * HD];     // layer output (post edge-agg + LN)
__device__ __align__(128) float g_s1[NN * HH];
__device__ __align__(128) float g_s2[NN * HH];
__device__ __align__(128) float g_Wp[HD * HD];    // packed W: [k][h*64+d]
__device__ __align__(128) float g_embT[EMBD * VV];// transposed embedding [c][v]
__device__ int g_rowptr[NN + 1];

// ---- packed f32x2 helpers (sm_103a) ----
__device__ __forceinline__ ull pk2(float x, float y) {
    ull r; asm("mov.b64 %0,{%1,%2};" : "=l"(r) : "f"(x), "f"(y)); return r;
}
__device__ __forceinline__ void fma2(ull& d, ull a, ull b) {
    asm("fma.rn.f32x2 %0,%1,%2,%0;" : "+l"(d) : "l"(a), "l"(b));
}
__device__ __forceinline__ void add2(ull& d, ull a) {
    asm("add.rn.f32x2 %0,%0,%1;" : "+l"(d) : "l"(a));
}
__device__ __forceinline__ float2 up2(ull v) {
    float2 f; asm("mov.b64 {%0,%1},%2;" : "=f"(f.x), "=f"(f.y) : "l"(v)); return f;
}

// ---- row_ptr from sorted edge_row via binary search ----
__global__ void k_rowptr(const int* __restrict__ er) {
    int r = blockIdx.x * blockDim.x + threadIdx.x;
    if (r > NN) return;
    int lo = 0, hi = EE;
    while (lo < hi) { int mid = (lo + hi) >> 1; if (er[mid] < r) lo = mid + 1; else hi = mid; }
    g_rowptr[r] = lo;
}

// ---- transpose emb (V,16) -> g_embT (16,V); 256 v-rows per block ----
__global__ void k_tr(const float* __restrict__ emb) {
    __shared__ float t[256][17];
    const int tid = threadIdx.x;
    const int v0 = blockIdx.x << 8;
#pragma unroll
    for (int p = 0; p < 16; ++p) {
        int idx = p * 256 + tid;                 // linear over 256x16 tile
        t[idx >> 4][idx & 15] = emb[(size_t)v0 * EMBD + idx];
    }
    __syncthreads();
#pragma unroll
    for (int p = 0; p < 16; ++p) {
        int idx = p * 256 + tid;                 // c = idx>>8, v = idx&255
        g_embT[(size_t)(idx >> 8) * VV + v0 + (idx & 255)] = t[idx & 255][idx >> 8];
    }
}

// ---- x = LN(x_in @ emb): 16 rows/block, 256 thr = 4 rowgroups x 64 v-lanes ----
__global__ void k_emb(const float* __restrict__ xin) {
    const int tid = threadIdx.x;
    const int rg = tid >> 6;        // rowgroup 0..3 (4 rows each)
    const int vl = tid & 63;        // v-lane
    const int R0 = blockIdx.x << 4;

    ull acc[4][8];
#pragma unroll
    for (int r = 0; r < 4; ++r)
#pragma unroll
        for (int c = 0; c < 8; ++c) acc[r][c] = 0ull;

    const size_t xbase = (size_t)(R0 + rg * 4) * VV;
    for (int it = 0; it < VV / 64; ++it) {
        const int v = vl + (it << 6);
        float ev[16];
#pragma unroll
        for (int c = 0; c < 16; ++c) ev[c] = g_embT[(size_t)c * VV + v];
        ull evq[8];
#pragma unroll
        for (int cp = 0; cp < 8; ++cp) evq[cp] = pk2(ev[2 * cp], ev[2 * cp + 1]);
#pragma unroll
        for (int r = 0; r < 4; ++r) {
            float xv = xin[xbase + (size_t)r * VV + v];
            ull xp = pk2(xv, xv);
#pragma unroll
            for (int cp = 0; cp < 8; ++cp) fma2(acc[r][cp], xp, evq[cp]);
        }
    }
    // reduce over 64 v-lanes: warp butterfly on packed pairs, then 2 halves via shared
    const int lane = tid & 31;
#pragma unroll
    for (int s = 16; s > 0; s >>= 1)
#pragma unroll
        for (int r = 0; r < 4; ++r)
#pragma unroll
            for (int c = 0; c < 8; ++c) {
                ull o = __shfl_xor_sync(0xffffffffu, acc[r][c], s);
                add2(acc[r][c], o);
            }

    __shared__ ull redq[4][2][32];    // [rowgroup][warp-half][r*8+cp]
    __shared__ float sval[16][17];
    __shared__ float smu[16], srs[16];
    const int half = vl >> 5;
    if (lane == 0) {
#pragma unroll
        for (int r = 0; r < 4; ++r)
#pragma unroll
            for (int c = 0; c < 8; ++c) redq[rg][half][r * 8 + c] = acc[r][c];
    }
    __syncthreads();
    {
        const int rl = tid >> 4, c = tid & 15;   // 16 rows x 16 cols
        const float* f0 = (const float*)redq[rl >> 2][0];
        const float* f1 = (const float*)redq[rl >> 2][1];
        const int idx = (rl & 3) * 16 + c;
        sval[rl][c] = f0[idx] + f1[idx];
    }
    __syncthreads();
    if (tid < 16) {
        float s = 0.f;
#pragma unroll
        for (int c = 0; c < 16; ++c) s += sval[tid][c];
        float mu = s * (1.f / 16);
        float var = 0.f;
#pragma unroll
        for (int c = 0; c < 16; ++c) { float d = sval[tid][c] - mu; var += d * d; }
        smu[tid] = mu;
        srs[tid] = rsqrtf(var * (1.f / 16) + 1e-5f);
    }
    __syncthreads();
    {
        const int rl = tid >> 4, c = tid & 15;
        g_xemb[(size_t)(R0 + rl) * EMBD + c] = (sval[rl][c] - smu[rl]) * srs[rl];
    }
}

// ---- layer-1: g_h = g_xemb (N,16) @ W1, W1 (H,16,64) -> cols h*64+d ----
__global__ void k_h1(const float* __restrict__ W1) {
    __shared__ float Ws[EMBD][HD];    // [k][h*64+d]
    __shared__ float xs[16][EMBD];
    const int tid = threadIdx.x;
    for (int i = tid; i < HH * EMBD * DD; i += 256) {
        int h = i >> 10, k = (i >> 6) & 15, d = i & 63;
        Ws[k][h * DD + d] = W1[i];
    }
    const int n0 = blockIdx.x << 4;   // 16 nodes per block
    for (int i = tid; i < 16 * EMBD; i += 256)
        xs[i >> 4][i & 15] = g_xemb[(size_t)n0 * EMBD + i];
    __syncthreads();
    const int c0 = tid * 2;
    for (int nl = 0; nl < 16; ++nl) {
        float a0 = 0.f, a1 = 0.f;
#pragma unroll
        for (int k = 0; k < EMBD; ++k) {
            float xv = xs[nl][k];
            a0 += xv * Ws[k][c0];
            a1 += xv * Ws[k][c0 + 1];
        }
        float2 o = make_float2(a0, a1);
        ((float2*)g_h)[(size_t)(n0 + nl) * 256 + tid] = o;
    }
}

// ---- per-node attention scalars: thread per (n,h); 16 independent float4 loads ----
__global__ void k_s(const float* __restrict__ av) {
    __shared__ float as1[HH * DD], as2[HH * DD];
    const int tid = threadIdx.x;
    for (int i = tid; i < HH * DD; i += 256) {
        as1[i] = av[(i >> 6) * 2 * DD + (i & 63)];
        as2[i] = av[(i >> 6) * 2 * DD + DD + (i & 63)];
    }
    __syncthreads();
    const int i = blockIdx.x * 256 + tid;        // 0..N*H-1
    const int n = i >> 3, h = i & 7;
    const float4* hp = (const float4*)(g_h + (size_t)n * HD + h * DD);
    const float* a1 = as1 + h * DD;
    const float* a2 = as2 + h * DD;
    float s1a = 0.f, s1b = 0.f, s2a = 0.f, s2b = 0.f;
#pragma unroll
    for (int j = 0; j < 16; j += 2) {
        float4 v = hp[j];
        s1a += v.x * a1[4*j] + v.y * a1[4*j+1] + v.z * a1[4*j+2] + v.w * a1[4*j+3];
        s2a += v.x * a2[4*j] + v.y * a2[4*j+1] + v.z * a2[4*j+2] + v.w * a2[4*j+3];
        float4 w = hp[j + 1];
        s1b += w.x * a1[4*j+4] + w.y * a1[4*j+5] + w.z * a1[4*j+6] + w.w * a1[4*j+7];
        s2b += w.x * a2[4*j+4] + w.y * a2[4*j+5] + w.z * a2[4*j+6] + w.w * a2[4*j+7];
    }
    g_s1[i] = s1a + s1b;
    g_s2[i] = s2a + s2b;
}

// ---- edge aggregation + normalize + (elu) + LN(512) + (elu); warp per row ----
// mode 0: elu then LN (layers 1,2).  mode 1: LN then elu (final layer).
__global__ void k_edge(const int* __restrict__ ecol, int mode) {
    const int warp = threadIdx.x >> 5, lane = threadIdx.x & 31;
    const int n = (blockIdx.x << 3) + warp;
    const int h = lane >> 2;                      // head of this lane's 16 cols
    const int start = g_rowptr[n], end = g_rowptr[n + 1];
    const float s1v = g_s1[n * HH + h];

    float acc[16];
#pragma unroll
    for (int j = 0; j < 16; ++j) acc[j] = 0.f;
    float rsum = 0.f;

    int c = (start < end) ? ecol[start] : 0;
    for (int e = start; e < end; ++e) {
        const int cn = (e + 1 < end) ? ecol[e + 1] : c;   // prefetch next index
        float t = s1v + g_s2[c * HH + h];
        float lr = t > 0.f ? t : 0.2f * t;
        float ev = __expf(-lr);
        rsum += ev;
        const float4* hp = (const float4*)(g_h + (size_t)c * HD + lane * 16);
#pragma unroll
        for (int j = 0; j < 4; ++j) {
            float4 v = hp[j];
            acc[4*j]   += ev * v.x;  acc[4*j+1] += ev * v.y;
            acc[4*j+2] += ev * v.z;  acc[4*j+3] += ev * v.w;
        }
        c = cn;
    }
    const float inv = 1.f / rsum;
    float o[16];
#pragma unroll
    for (int j = 0; j < 16; ++j) {
        float v = acc[j] * inv;
        if (mode == 0) v = v > 0.f ? v : expm1f(v);   // elu before LN
        o[j] = v;
    }
    // LayerNorm over the full 512 (warp holds the row)
    float s = 0.f, sq = 0.f;
#pragma unroll
    for (int j = 0; j < 16; ++j) { s += o[j]; sq += o[j] * o[j]; }
#pragma unroll
    for (int d = 16; d > 0; d >>= 1) {
        s  += __shfl_xor_sync(0xffffffffu, s, d);
        sq += __shfl_xor_sync(0xffffffffu, sq, d);
    }
    float mu = s * (1.f / HD);
    float var = sq * (1.f / HD) - mu * mu;
    float rs = rsqrtf(var + 1e-5f);
    float* xo = g_x + (size_t)n * HD + lane * 16;
#pragma unroll
    for (int j = 0; j < 16; ++j) {
        float v = (o[j] - mu) * rs;
        if (mode == 1) v = v > 0.f ? v : expm1f(v);   // elu after LN (final)
        xo[j] = v;
    }
}

// ---- pack W (H,512,64) -> Wp[k][h*64+d] ----
__global__ void k_pack(const float* __restrict__ W) {
    int i = blockIdx.x * 256 + threadIdx.x;
    int h = i >> 15, k = (i >> 6) & 511, d = i & 63;
    g_Wp[k * HD + (h << 6) + d] = W[i];
}

// ---- g_h = g_x (N,512) @ g_Wp; 256x128 block tile, BK=16, f32x2 FMAs ----
// Rows packed as pairs (m, m+128) inside ull accumulators; B stored broadcast-
// duplicated in smem so the inner loop is pure LDS.64 + fma.rn.f32x2.
__global__ void __launch_bounds__(256, 1) k_gemm() {
    __shared__ ull AsU[16][128];      // [k][q]: pair (row m0+q, m0+q+128)
    __shared__ ull BsB[16][128];      // [k][c]: pk2(w, w)
    const int tid = threadIdx.x;
    const int tx = tid & 15, ty = tid >> 4;
    const int m0 = blockIdx.y * 256, n0 = blockIdx.x * 128;
    ull acc[8][8];
#pragma unroll
    for (int i = 0; i < 8; ++i)
#pragma unroll
        for (int j = 0; j < 8; ++j) acc[i][j] = 0ull;

    float* As_f = (float*)AsU;        // [k][q*2+half]

    for (int k0 = 0; k0 < HD; k0 += 16) {
        // fill A: thread tid loads row m0+tid, 16 k-values
        {
            const int r = tid;
            const int qf = ((r & 127) << 1) | (r >> 7);
#pragma unroll
            for (int c2 = 0; c2 < 4; ++c2) {
                float4 a = *(const float4*)(g_x + (size_t)(m0 + r) * HD + k0 + c2 * 4);
                As_f[(c2 * 4 + 0) * 256 + qf] = a.x;
                As_f[(c2 * 4 + 1) * 256 + qf] = a.y;
                As_f[(c2 * 4 + 2) * 256 + qf] = a.z;
                As_f[(c2 * 4 + 3) * 256 + qf] = a.w;
            }
            // fill B broadcast-duplicated
            const int kb = tid >> 5, cb = (tid & 31) * 4;
#pragma unroll
            for (int p = 0; p < 2; ++p) {
                float4 b = *(const float4*)(g_Wp + (size_t)(k0 + kb + p * 8) * HD + n0 + cb);
                BsB[kb + p * 8][cb + 0] = pk2(b.x, b.x);
                BsB[kb + p * 8][cb + 1] = pk2(b.y, b.y);
                BsB[kb + p * 8][cb + 2] = pk2(b.z, b.z);
                BsB[kb + p * 8][cb + 3] = pk2(b.w, b.w);
            }
        }
        __syncthreads();
#pragma unroll 4
        for (int k = 0; k < 16; ++k) {
            ull raq[8], rbq[8];
#pragma unroll
            for (int ip = 0; ip < 8; ++ip) raq[ip] = AsU[k][ty + 16 * ip];
#pragma unroll
            for (int j = 0; j < 8; ++j) rbq[j] = BsB[k][tx + 16 * j];
#pragma unroll
            for (int ip = 0; ip < 8; ++ip)
#pragma unroll
                for (int j = 0; j < 8; ++j) fma2(acc[ip][j], raq[ip], rbq[j]);
        }
        __syncthreads();
    }
#pragma unroll
    for (int ip = 0; ip < 8; ++ip) {
        const int m = m0 + ty + 16 * ip;
#pragma unroll
        for (int j = 0; j < 8; ++j) {
            float2 v = up2(acc[ip][j]);
            g_h[(size_t)m * HD + n0 + tx + 16 * j] = v.x;
            g_h[(size_t)(m + 128) * HD + n0 + tx + 16 * j] = v.y;
        }
    }
}

// ---- classifier + log_softmax; warp per row ----
__global__ void k_out(const float* __restrict__ Wo, const float* __restrict__ bo,
                      float* __restrict__ out) {
    const int warp = threadIdx.x >> 5, lane = threadIdx.x & 31;
    const int n = (blockIdx.x << 3) + warp;
    const int c1 = 32 + (lane & 7);           // always in-bounds
    const float* xr = g_x + (size_t)n * HD;
    float a0 = 0.f, a1 = 0.f;
    for (int k = 0; k < HD; ++k) {
        float xv = xr[k];
        a0 += xv * Wo[k * NC + lane];
        a1 += xv * Wo[k * NC + c1];
    }
    float v0 = a0 + bo[lane];
    float v1 = a1 + bo[c1];
    bool use1 = lane < 8;
    float m = fmaxf(v0, use1 ? v1 : -3.4e38f);
#pragma unroll
    for (int d = 16; d > 0; d >>= 1) m = fmaxf(m, __shfl_xor_sync(0xffffffffu, m, d));
    float se = expf(v0 - m) + (use1 ? expf(v1 - m) : 0.f);
#pragma unroll
    for (int d = 16; d > 0; d >>= 1) se += __shfl_xor_sync(0xffffffffu, se, d);
    float lse = m + logf(se);
    out[(size_t)n * NC + lane] = v0 - lse;
    if (use1) out[(size_t)n * NC + c1] = v1 - lse;
}

extern "C" void kernel_launch(void* const* d_in, const int* in_sizes, int n_in,
                              void* d_out, int out_size) {
    const float* x_in = (const float*)d_in[0];
    const float* emb  = (const float*)d_in[1];
    const float* W1   = (const float*)d_in[2];
    const float* a1   = (const float*)d_in[3];
    const float* W2   = (const float*)d_in[4];
    const float* a2   = (const float*)d_in[5];
    const float* Wf   = (const float*)d_in[6];
    const float* af   = (const float*)d_in[7];
    const float* Wo   = (const float*)d_in[8];
    const float* bo   = (const float*)d_in[9];
    const int* erow   = (const int*)d_in[10];
    const int* ecol   = (const int*)d_in[11];
    float* out = (float*)d_out;

    k_rowptr<<<65, 256>>>(erow);
    k_tr<<<VV / 256, 256>>>(emb);
    k_emb<<<NN / 16, 256>>>(x_in);

    // layer 1
    k_h1<<<NN / 16, 256>>>(W1);
    k_s<<<NN * HH / 256, 256>>>(a1);
    k_edge<<<NN / 8, 256>>>(ecol, 0);
    // layer 2
    k_pack<<<HD * HD / 256, 256>>>(W2);
    k_gemm<<<dim3(4, 64), 256>>>();
    k_s<<<NN * HH / 256, 256>>>(a2);
    k_edge<<<NN / 8, 256>>>(ecol, 0);
    // final GAT layer
    k_pack<<<HD * HD / 256, 256>>>(Wf);
    k_gemm<<<dim3(4, 64), 256>>>();
    k_s<<<NN * HH / 256, 256>>>(af);
    k_edge<<<NN / 8, 256>>>(ecol, 1);
    // classifier
    k_out<<<NN / 8, 256>>>(Wo, bo, out);
}

// round 6
// speedup vs baseline: 1.1570x; 1.1178x over previous
#include <cuda_runtime.h>
#include <cuda_bf16.h>
#include <mma.h>

using namespace nvcuda;

#define NN 16384
#define VV 16384
#define EE 524288
#define HH 8
#define DD 64
#define HD 512
#define EMBD 16
#define NC 40

typedef unsigned long long ull;

// ---- scratch (device globals; allocation is forbidden) ----
__device__ __align__(128) float g_xemb[NN * EMBD];
__device__ __align__(128) float g_h[NN * HD];     // transformed features (x @ W)
__device__ __align__(128) float g_x[NN * HD];     // layer output (post edge-agg + LN)
__device__ __align__(128) float g_s1[NN * HH];
__device__ __align__(128) float g_s2[NN * HH];
__device__ __align__(128) float g_Wp[HD * HD];    // packed W: [k][h*64+d]
__device__ __align__(128) float g_embT[EMBD * VV];// transposed embedding [c][v]
__device__ int g_rowptr[NN + 1];

// ---- packed f32x2 helpers (sm_103a) ----
__device__ __forceinline__ ull pk2(float x, float y) {
    ull r; asm("mov.b64 %0,{%1,%2};" : "=l"(r) : "f"(x), "f"(y)); return r;
}
__device__ __forceinline__ void fma2(ull& d, ull a, ull b) {
    asm("fma.rn.f32x2 %0,%1,%2,%0;" : "+l"(d) : "l"(a), "l"(b));
}
__device__ __forceinline__ void add2(ull& d, ull a) {
    asm("add.rn.f32x2 %0,%0,%1;" : "+l"(d) : "l"(a));
}

// ---- row_ptr from sorted edge_row via binary search ----
__global__ void k_rowptr(const int* __restrict__ er) {
    int r = blockIdx.x * blockDim.x + threadIdx.x;
    if (r > NN) return;
    int lo = 0, hi = EE;
    while (lo < hi) { int mid = (lo + hi) >> 1; if (er[mid] < r) lo = mid + 1; else hi = mid; }
    g_rowptr[r] = lo;
}

// ---- transpose emb (V,16) -> g_embT (16,V) ----
__global__ void k_tr(const float* __restrict__ emb) {
    __shared__ float t[256][17];
    const int tid = threadIdx.x;
    const int v0 = blockIdx.x << 8;
#pragma unroll
    for (int p = 0; p < 16; ++p) {
        int idx = p * 256 + tid;
        t[idx >> 4][idx & 15] = emb[(size_t)v0 * EMBD + idx];
    }
    __syncthreads();
#pragma unroll
    for (int p = 0; p < 16; ++p) {
        int idx = p * 256 + tid;
        g_embT[(size_t)(idx >> 8) * VV + v0 + (idx & 255)] = t[idx & 255][idx >> 8];
    }
}

// ---- x = LN(x_in @ emb): 16 rows/block; float4 streaming of x_in ----
__global__ void __launch_bounds__(256) k_emb(const float* __restrict__ xin) {
    const int tid = threadIdx.x;
    const int rg = tid >> 6;        // rowgroup 0..3 (4 rows each)
    const int vl = tid & 63;        // v-lane (handles 4 consecutive v)
    const int R0 = blockIdx.x << 4;

    ull acc[4][8];
#pragma unroll
    for (int r = 0; r < 4; ++r)
#pragma unroll
        for (int c = 0; c < 8; ++c) acc[r][c] = 0ull;

    const size_t xbase = (size_t)(R0 + rg * 4) * VV;
    for (int it = 0; it < VV / 256; ++it) {
        const int v = (vl << 2) + (it << 8);
        float4 xv[4];
#pragma unroll
        for (int r = 0; r < 4; ++r)
            xv[r] = *(const float4*)(xin + xbase + (size_t)r * VV + v);

        // half 0: emb cols 0..7 -> acc[.][0..3]
        {
            float4 ef[8];
#pragma unroll
            for (int c = 0; c < 8; ++c) ef[c] = *(const float4*)(g_embT + (size_t)c * VV + v);
#pragma unroll
            for (int j = 0; j < 4; ++j) {
                ull evq[4];
#pragma unroll
                for (int cp = 0; cp < 4; ++cp)
                    evq[cp] = pk2(((const float*)&ef[2 * cp])[j], ((const float*)&ef[2 * cp + 1])[j]);
#pragma unroll
                for (int r = 0; r < 4; ++r) {
                    float xj = ((const float*)&xv[r])[j];
                    ull xp = pk2(xj, xj);
#pragma unroll
                    for (int cp = 0; cp < 4; ++cp) fma2(acc[r][cp], xp, evq[cp]);
                }
            }
        }
        // half 1: emb cols 8..15 -> acc[.][4..7]
        {
            float4 ef[8];
#pragma unroll
            for (int c = 0; c < 8; ++c) ef[c] = *(const float4*)(g_embT + (size_t)(c + 8) * VV + v);
#pragma unroll
            for (int j = 0; j < 4; ++j) {
                ull evq[4];
#pragma unroll
                for (int cp = 0; cp < 4; ++cp)
                    evq[cp] = pk2(((const float*)&ef[2 * cp])[j], ((const float*)&ef[2 * cp + 1])[j]);
#pragma unroll
                for (int r = 0; r < 4; ++r) {
                    float xj = ((const float*)&xv[r])[j];
                    ull xp = pk2(xj, xj);
#pragma unroll
                    for (int cp = 0; cp < 4; ++cp) fma2(acc[r][cp + 4], xp, evq[cp]);
                }
            }
        }
    }
    // reduce over 64 v-lanes: warp butterfly on packed pairs, then 2 halves via shared
    const int lane = tid & 31;
#pragma unroll
    for (int s = 16; s > 0; s >>= 1)
#pragma unroll
        for (int r = 0; r < 4; ++r)
#pragma unroll
            for (int c = 0; c < 8; ++c) {
                ull o = __shfl_xor_sync(0xffffffffu, acc[r][c], s);
                add2(acc[r][c], o);
            }

    __shared__ ull redq[4][2][32];    // [rowgroup][warp-half][r*8+cp]
    __shared__ float sval[16][17];
    __shared__ float smu[16], srs[16];
    const int half = vl >> 5;
    if (lane == 0) {
#pragma unroll
        for (int r = 0; r < 4; ++r)
#pragma unroll
            for (int c = 0; c < 8; ++c) redq[rg][half][r * 8 + c] = acc[r][c];
    }
    __syncthreads();
    {
        const int rl = tid >> 4, c = tid & 15;   // 16 rows x 16 cols
        const float* f0 = (const float*)redq[rl >> 2][0];
        const float* f1 = (const float*)redq[rl >> 2][1];
        const int idx = (rl & 3) * 16 + c;
        sval[rl][c] = f0[idx] + f1[idx];
    }
    __syncthreads();
    if (tid < 16) {
        float s = 0.f;
#pragma unroll
        for (int c = 0; c < 16; ++c) s += sval[tid][c];
        float mu = s * (1.f / 16);
        float var = 0.f;
#pragma unroll
        for (int c = 0; c < 16; ++c) { float d = sval[tid][c] - mu; var += d * d; }
        smu[tid] = mu;
        srs[tid] = rsqrtf(var * (1.f / 16) + 1e-5f);
    }
    __syncthreads();
    {
        const int rl = tid >> 4, c = tid & 15;
        g_xemb[(size_t)(R0 + rl) * EMBD + c] = (sval[rl][c] - smu[rl]) * srs[rl];
    }
}

// ---- layer-1: g_h = g_xemb (N,16) @ W1 ----
__global__ void k_h1(const float* __restrict__ W1) {
    __shared__ float Ws[EMBD][HD];
    __shared__ float xs[16][EMBD];
    const int tid = threadIdx.x;
    for (int i = tid; i < HH * EMBD * DD; i += 256) {
        int h = i >> 10, k = (i >> 6) & 15, d = i & 63;
        Ws[k][h * DD + d] = W1[i];
    }
    const int n0 = blockIdx.x << 4;
    for (int i = tid; i < 16 * EMBD; i += 256)
        xs[i >> 4][i & 15] = g_xemb[(size_t)n0 * EMBD + i];
    __syncthreads();
    const int c0 = tid * 2;
    for (int nl = 0; nl < 16; ++nl) {
        float a0 = 0.f, a1 = 0.f;
#pragma unroll
        for (int k = 0; k < EMBD; ++k) {
            float xv = xs[nl][k];
            a0 += xv * Ws[k][c0];
            a1 += xv * Ws[k][c0 + 1];
        }
        ((float2*)g_h)[(size_t)(n0 + nl) * 256 + tid] = make_float2(a0, a1);
    }
}

// ---- per-node attention scalars: thread per (n,h) ----
__global__ void k_s(const float* __restrict__ av) {
    __shared__ float as1[HH * DD], as2[HH * DD];
    const int tid = threadIdx.x;
    for (int i = tid; i < HH * DD; i += 256) {
        as1[i] = av[(i >> 6) * 2 * DD + (i & 63)];
        as2[i] = av[(i >> 6) * 2 * DD + DD + (i & 63)];
    }
    __syncthreads();
    const int i = blockIdx.x * 256 + tid;
    const int n = i >> 3, h = i & 7;
    const float4* hp = (const float4*)(g_h + (size_t)n * HD + h * DD);
    const float* a1 = as1 + h * DD;
    const float* a2 = as2 + h * DD;
    float s1a = 0.f, s1b = 0.f, s2a = 0.f, s2b = 0.f;
#pragma unroll
    for (int j = 0; j < 16; j += 2) {
        float4 v = hp[j];
        s1a += v.x * a1[4*j] + v.y * a1[4*j+1] + v.z * a1[4*j+2] + v.w * a1[4*j+3];
        s2a += v.x * a2[4*j] + v.y * a2[4*j+1] + v.z * a2[4*j+2] + v.w * a2[4*j+3];
        float4 w = hp[j + 1];
        s1b += w.x * a1[4*j+4] + w.y * a1[4*j+5] + w.z * a1[4*j+6] + w.w * a1[4*j+7];
        s2b += w.x * a2[4*j+4] + w.y * a2[4*j+5] + w.z * a2[4*j+6] + w.w * a2[4*j+7];
    }
    g_s1[i] = s1a + s1b;
    g_s2[i] = s2a + s2b;
}

// ---- edge aggregation + normalize + (elu) + LN(512) + (elu); warp per row ----
__global__ void k_edge(const int* __restrict__ ecol, int mode) {
    const int warp = threadIdx.x >> 5, lane = threadIdx.x & 31;
    const int n = (blockIdx.x << 3) + warp;
    const int h = lane >> 2;
    const int start = g_rowptr[n], end = g_rowptr[n + 1];
    const float s1v = g_s1[n * HH + h];

    float acc[16];
#pragma unroll
    for (int j = 0; j < 16; ++j) acc[j] = 0.f;
    float rsum = 0.f;

    int e = start;
    for (; e + 2 <= end; e += 2) {          // two edges in flight
        const int c0 = ecol[e], c1 = ecol[e + 1];
        float t0 = s1v + g_s2[c0 * HH + h];
        float t1 = s1v + g_s2[c1 * HH + h];
        float ev0 = __expf(-(t0 > 0.f ? t0 : 0.2f * t0));
        float ev1 = __expf(-(t1 > 0.f ? t1 : 0.2f * t1));
        rsum += ev0 + ev1;
        const float4* h0 = (const float4*)(g_h + (size_t)c0 * HD + lane * 16);
        const float4* h1 = (const float4*)(g_h + (size_t)c1 * HD + lane * 16);
#pragma unroll
        for (int j = 0; j < 4; ++j) {
            float4 v0 = h0[j], v1 = h1[j];
            acc[4*j]   += ev0 * v0.x + ev1 * v1.x;
            acc[4*j+1] += ev0 * v0.y + ev1 * v1.y;
            acc[4*j+2] += ev0 * v0.z + ev1 * v1.z;
            acc[4*j+3] += ev0 * v0.w + ev1 * v1.w;
        }
    }
    if (e < end) {
        const int c0 = ecol[e];
        float t0 = s1v + g_s2[c0 * HH + h];
        float ev0 = __expf(-(t0 > 0.f ? t0 : 0.2f * t0));
        rsum += ev0;
        const float4* h0 = (const float4*)(g_h + (size_t)c0 * HD + lane * 16);
#pragma unroll
        for (int j = 0; j < 4; ++j) {
            float4 v0 = h0[j];
            acc[4*j]   += ev0 * v0.x;  acc[4*j+1] += ev0 * v0.y;
            acc[4*j+2] += ev0 * v0.z;  acc[4*j+3] += ev0 * v0.w;
        }
    }
    const float inv = 1.f / rsum;
    float o[16];
#pragma unroll
    for (int j = 0; j < 16; ++j) {
        float v = acc[j] * inv;
        if (mode == 0) v = v > 0.f ? v : expm1f(v);
        o[j] = v;
    }
    float s = 0.f, sq = 0.f;
#pragma unroll
    for (int j = 0; j < 16; ++j) { s += o[j]; sq += o[j] * o[j]; }
#pragma unroll
    for (int d = 16; d > 0; d >>= 1) {
        s  += __shfl_xor_sync(0xffffffffu, s, d);
        sq += __shfl_xor_sync(0xffffffffu, sq, d);
    }
    float mu = s * (1.f / HD);
    float var = sq * (1.f / HD) - mu * mu;
    float rs = rsqrtf(var + 1e-5f);
    float* xo = g_x + (size_t)n * HD + lane * 16;
#pragma unroll
    for (int j = 0; j < 16; ++j) {
        float v = (o[j] - mu) * rs;
        if (mode == 1) v = v > 0.f ? v : expm1f(v);
        xo[j] = v;
    }
}

// ---- pack W (H,512,64) -> Wp[k][h*64+d] ----
__global__ void k_pack(const float* __restrict__ W) {
    int i = blockIdx.x * 256 + threadIdx.x;
    int h = i >> 15, k = (i >> 6) & 511, d = i & 63;
    g_Wp[k * HD + (h << 6) + d] = W[i];
}

// ---- tf32 tensor-core GEMM: g_h = g_x (N,512) @ g_Wp (512,512) ----
// 128x128 block tile, BK=32; 8 warps as 4x2, each warp 32x64 (2x4 m16n16k8 frags)
__global__ void __launch_bounds__(256) k_gemm() {
    __shared__ float As[128][40];     // m x k, pad 8 (row = 160 B, 16B aligned)
    __shared__ float Bs[32][136];     // k x n, pad 8 (row = 544 B, 16B aligned)
    const int tid = threadIdx.x;
    const int warp = tid >> 5;
    const int wm = warp >> 1, wn = warp & 1;
    const int m0 = blockIdx.y * 128, n0 = blockIdx.x * 128;

    wmma::fragment<wmma::accumulator, 16, 16, 8, float> c[2][4];
#pragma unroll
    for (int i = 0; i < 2; ++i)
#pragma unroll
        for (int j = 0; j < 4; ++j) wmma::fill_fragment(c[i][j], 0.f);

    for (int k0 = 0; k0 < HD; k0 += 32) {
        // stage A 128x32
#pragma unroll
        for (int p = 0; p < 4; ++p) {
            int idx = tid + p * 256;
            int row = idx >> 3, col = (idx & 7) * 4;
            float4 a = *(const float4*)(g_x + (size_t)(m0 + row) * HD + k0 + col);
            *(float4*)&As[row][col] = a;
        }
        // stage B 32x128
#pragma unroll
        for (int p = 0; p < 4; ++p) {
            int idx = tid + p * 256;
            int row = idx >> 5, col = (idx & 31) * 4;
            float4 b = *(const float4*)(g_Wp + (size_t)(k0 + row) * HD + n0 + col);
            *(float4*)&Bs[row][col] = b;
        }
        __syncthreads();
#pragma unroll
        for (int kk = 0; kk < 32; kk += 8) {
            wmma::fragment<wmma::matrix_a, 16, 16, 8, wmma::precision::tf32, wmma::row_major> a[2];
            wmma::fragment<wmma::matrix_b, 16, 16, 8, wmma::precision::tf32, wmma::row_major> b[4];
#pragma unroll
            for (int i = 0; i < 2; ++i) {
                wmma::load_matrix_sync(a[i], &As[wm * 32 + i * 16][kk], 40);
#pragma unroll
                for (int t = 0; t < a[i].num_elements; ++t)
                    a[i].x[t] = wmma::__float_to_tf32(a[i].x[t]);
            }
#pragma unroll
            for (int j = 0; j < 4; ++j) {
                wmma::load_matrix_sync(b[j], &Bs[kk][wn * 64 + j * 16], 136);
#pragma unroll
                for (int t = 0; t < b[j].num_elements; ++t)
                    b[j].x[t] = wmma::__float_to_tf32(b[j].x[t]);
            }
#pragma unroll
            for (int i = 0; i < 2; ++i)
#pragma unroll
                for (int j = 0; j < 4; ++j)
                    wmma::mma_sync(c[i][j], a[i], b[j], c[i][j]);
        }
        __syncthreads();
    }
#pragma unroll
    for (int i = 0; i < 2; ++i)
#pragma unroll
        for (int j = 0; j < 4; ++j)
            wmma::store_matrix_sync(g_h + (size_t)(m0 + wm * 32 + i * 16) * HD + n0 + wn * 64 + j * 16,
                                    c[i][j], HD, wmma::mem_row_major);
}

// ---- classifier + log_softmax; warp per row ----
__global__ void k_out(const float* __restrict__ Wo, const float* __restrict__ bo,
                      float* __restrict__ out) {
    const int warp = threadIdx.x >> 5, lane = threadIdx.x & 31;
    const int n = (blockIdx.x << 3) + warp;
    const int c1 = 32 + (lane & 7);
    const float* xr = g_x + (size_t)n * HD;
    float a0 = 0.f, a1 = 0.f;
    for (int k = 0; k < HD; ++k) {
        float xv = xr[k];
        a0 += xv * Wo[k * NC + lane];
        a1 += xv * Wo[k * NC + c1];
    }
    float v0 = a0 + bo[lane];
    float v1 = a1 + bo[c1];
    bool use1 = lane < 8;
    float m = fmaxf(v0, use1 ? v1 : -3.4e38f);
#pragma unroll
    for (int d = 16; d > 0; d >>= 1) m = fmaxf(m, __shfl_xor_sync(0xffffffffu, m, d));
    float se = expf(v0 - m) + (use1 ? expf(v1 - m) : 0.f);
#pragma unroll
    for (int d = 16; d > 0; d >>= 1) se += __shfl_xor_sync(0xffffffffu, se, d);
    float lse = m + logf(se);
    out[(size_t)n * NC + lane] = v0 - lse;
    if (use1) out[(size_t)n * NC + c1] = v1 - lse;
}

extern "C" void kernel_launch(void* const* d_in, const int* in_sizes, int n_in,
                              void* d_out, int out_size) {
    const float* x_in = (const float*)d_in[0];
    const float* emb  = (const float*)d_in[1];
    const float* W1   = (const float*)d_in[2];
    const float* a1   = (const float*)d_in[3];
    const float* W2   = (const float*)d_in[4];
    const float* a2   = (const float*)d_in[5];
    const float* Wf   = (const float*)d_in[6];
    const float* af   = (const float*)d_in[7];
    const float* Wo   = (const float*)d_in[8];
    const float* bo   = (const float*)d_in[9];
    const int* erow   = (const int*)d_in[10];
    const int* ecol   = (const int*)d_in[11];
    float* out = (float*)d_out;

    k_rowptr<<<65, 256>>>(erow);
    k_tr<<<VV / 256, 256>>>(emb);
    k_emb<<<NN / 16, 256>>>(x_in);

    // layer 1
    k_h1<<<NN / 16, 256>>>(W1);
    k_s<<<NN * HH / 256, 256>>>(a1);
    k_edge<<<NN / 8, 256>>>(ecol, 0);
    // layer 2
    k_pack<<<HD * HD / 256, 256>>>(W2);
    k_gemm<<<dim3(4, 128), 256>>>();
    k_s<<<NN * HH / 256, 256>>>(a2);
    k_edge<<<NN / 8, 256>>>(ecol, 0);
    // final GAT layer
    k_pack<<<HD * HD / 256, 256>>>(Wf);
    k_gemm<<<dim3(4, 128), 256>>>();
    k_s<<<NN * HH / 256, 256>>>(af);
    k_edge<<<NN / 8, 256>>>(ecol, 1);
    // classifier
    k_out<<<NN / 8, 256>>>(Wo, bo, out);
}